// round 3
// baseline (speedup 1.0000x reference)
#include <cuda_runtime.h>
#include <cuda_bf16.h>
#include <cstdint>

// Problem constants (fixed shapes)
#define N0    260000
#define N1    10240
#define BSZ   1024
#define E0    256000
#define E1    10240
#define IN_C  602
#define HID   256
#define OUT_C 41

// Padded concat-K for layer-0 GEMM: [0,602)=agg, [602,608)=0, [608,1210)=x_tgt, [1210,1216)=0
#define KCAT  1216

// ---------------- scratch (static device memory; no allocation) ----------------
__device__ float g_acat[(size_t)N1 * KCAT];     // 49.8 MB  concat A for GEMM0
__device__ float g_wcat[(size_t)KCAT * HID];    // 1.2 MB   concat W for GEMM0
__device__ float g_h[(size_t)N1 * HID];         // 10.5 MB  layer-0 output (post ReLU)
__device__ float g_agg1[(size_t)BSZ * HID];     // 1 MB     layer-1 aggregation
__device__ int   g_seg0[N1 + 1];
__device__ int   g_seg1[BSZ + 1];

// ---------------- segment boundaries via binary search (dst is sorted) ----------------
__global__ void seg_kernel(const int* __restrict__ dst, int E, int Nt, int which) {
    int t = blockIdx.x * blockDim.x + threadIdx.x;
    if (t > Nt) return;
    int lo = 0, hi = E;
    while (lo < hi) {
        int mid = (lo + hi) >> 1;
        if (dst[mid] < t) lo = mid + 1; else hi = mid;
    }
    if (which == 0) g_seg0[t] = lo; else g_seg1[t] = lo;
}

// ---------------- build padded concat weight [KCAT][HID] ----------------
__global__ void wcat_kernel(const float* __restrict__ Wl0, const float* __restrict__ Wr0) {
    int k = blockIdx.x;        // 0..KCAT-1
    int n = threadIdx.x;       // 0..255
    float v = 0.f;
    if (k < IN_C)                    v = Wl0[(size_t)k * HID + n];
    else if (k >= 608 && k < 1210)   v = Wr0[(size_t)(k - 608) * HID + n];
    g_wcat[(size_t)k * HID + n] = v;
}

// ---------------- layer-0 mean aggregation + x_tgt copy into concat A ----------------
// one CTA per target node; 256 threads cover 602 features (256+256+90)
__global__ void __launch_bounds__(256) agg0_kernel(const float* __restrict__ x,
                                                   const int* __restrict__ src) {
    int t = blockIdx.x;
    int tid = threadIdx.x;
    int s = g_seg0[t], e = g_seg0[t + 1];
    __shared__ int sidx[256];

    float a0 = 0.f, a1 = 0.f, a2 = 0.f;
    for (int base = s; base < e; base += 256) {
        int n = min(256, e - base);
        if (tid < n) sidx[tid] = src[base + tid];
        __syncthreads();
#pragma unroll 4
        for (int i = 0; i < n; i++) {
            const float* row = x + (size_t)sidx[i] * IN_C;
            a0 += __ldg(row + tid);
            a1 += __ldg(row + tid + 256);
            if (tid < 90) a2 += __ldg(row + tid + 512);
        }
        __syncthreads();
    }
    float inv = (e > s) ? (1.0f / (float)(e - s)) : 1.0f;
    size_t off = (size_t)t * KCAT;
    g_acat[off + tid]       = a0 * inv;
    g_acat[off + 256 + tid] = a1 * inv;
    if (tid < 90) g_acat[off + 512 + tid] = a2 * inv;

    // x_tgt (first N1 rows of x) into cols [608,1210); pads [602,608),[1210,1216) = 0
    const float* xr = x + (size_t)t * IN_C;
    for (int j = 602 + tid; j < KCAT; j += 256) {
        int jj = j - 608;
        g_acat[off + j] = (jj >= 0 && jj < IN_C) ? xr[jj] : 0.f;
    }
}

// ---------------- layer-0 GEMM: h = relu(Acat @ Wcat + b_l0) ----------------
// 64x64 tile, BK=16, 256 threads, 4x4 micro-tile, packed fma.rn.f32x2 accumulators
#define BM 64
#define BN 64
#define BK 16
__global__ void __launch_bounds__(256) gemm0_kernel(const float* __restrict__ bias) {
    __shared__ float As[BK][BM + 4];   // +4 pad keeps float4 align, reduces store conflicts
    __shared__ float Bs[BK][BN];

    int tid = threadIdx.x;
    int m0 = blockIdx.x * BM;          // 160 m-tiles
    int n0 = blockIdx.y * BN;          // 4 n-tiles

    int ar = tid >> 2;                 // 0..63 (A row)
    int ak = (tid & 3) * 4;            // 0,4,8,12 (A k quad)
    int bkr = tid >> 4;                // 0..15 (B k row)
    int bnc = (tid & 15) * 4;          // 0..60 (B col quad)

    const float* Aptr = g_acat + (size_t)(m0 + ar) * KCAT + ak;
    const float* Bptr = g_wcat + (size_t)bkr * HID + n0 + bnc;

    int tx = tid & 15, ty = tid >> 4;

    unsigned long long c2[4][2] = {};  // 4 rows x 2 packed col-pairs (= 4x4 fp32)

    float4 aR = *(const float4*)Aptr;
    float4 bR = *(const float4*)Bptr;

    const int NIT = KCAT / BK;         // 76
    for (int it = 0; it < NIT; ++it) {
        As[ak + 0][ar] = aR.x; As[ak + 1][ar] = aR.y;
        As[ak + 2][ar] = aR.z; As[ak + 3][ar] = aR.w;
        *(float4*)&Bs[bkr][bnc] = bR;
        __syncthreads();

        if (it + 1 < NIT) {            // prefetch next tiles (overlaps compute)
            aR = *(const float4*)(Aptr + (it + 1) * BK);
            bR = *(const float4*)(Bptr + (size_t)(it + 1) * BK * HID);
        }

#pragma unroll
        for (int k = 0; k < BK; k++) {
            float4 av = *(const float4*)&As[k][ty * 4];
            ulonglong2 bv = *(const ulonglong2*)&Bs[k][tx * 4];  // 2 packed f32 pairs
            float aa[4] = {av.x, av.y, av.z, av.w};
#pragma unroll
            for (int i = 0; i < 4; i++) {
                unsigned long long ad;
                asm("mov.b64 %0, {%1, %1};" : "=l"(ad) : "f"(aa[i]));
                asm("fma.rn.f32x2 %0, %1, %2, %0;" : "+l"(c2[i][0]) : "l"(ad), "l"(bv.x));
                asm("fma.rn.f32x2 %0, %1, %2, %0;" : "+l"(c2[i][1]) : "l"(ad), "l"(bv.y));
            }
        }
        __syncthreads();
    }

    float4 bb = *(const float4*)&bias[n0 + tx * 4];
#pragma unroll
    for (int i = 0; i < 4; i++) {
        float r0, r1, r2, r3;
        asm("mov.b64 {%0, %1}, %2;" : "=f"(r0), "=f"(r1) : "l"(c2[i][0]));
        asm("mov.b64 {%0, %1}, %2;" : "=f"(r2), "=f"(r3) : "l"(c2[i][1]));
        float4 o;
        o.x = fmaxf(r0 + bb.x, 0.f);
        o.y = fmaxf(r1 + bb.y, 0.f);
        o.z = fmaxf(r2 + bb.z, 0.f);
        o.w = fmaxf(r3 + bb.w, 0.f);
        int m = m0 + ty * 4 + i;
        *(float4*)&g_h[(size_t)m * HID + n0 + tx * 4] = o;
    }
}

// ---------------- layer-1 mean aggregation: agg1[t][f] = mean_{e: dst1[e]=t} h[src1[e]][f] ----------------
__global__ void __launch_bounds__(256) agg1_kernel(const int* __restrict__ src) {
    int t = blockIdx.x;
    int tid = threadIdx.x;
    int s = g_seg1[t], e = g_seg1[t + 1];
    __shared__ int sidx[256];
    float a = 0.f;
    for (int base = s; base < e; base += 256) {
        int n = min(256, e - base);
        if (tid < n) sidx[tid] = src[base + tid];
        __syncthreads();
#pragma unroll 4
        for (int i = 0; i < n; i++)
            a += g_h[(size_t)sidx[i] * HID + tid];
        __syncthreads();
    }
    float inv = (e > s) ? (1.0f / (float)(e - s)) : 1.0f;
    g_agg1[(size_t)t * HID + tid] = a * inv;
}

// ---------------- layer-1 GEMM + log_softmax, one CTA per output row ----------------
__global__ void __launch_bounds__(256) out_kernel(const float* __restrict__ Wl1,
                                                  const float* __restrict__ Wr1,
                                                  const float* __restrict__ bl1,
                                                  float* __restrict__ out) {
    int t = blockIdx.x;
    int tid = threadIdx.x;
    __shared__ float av[2 * HID];
    __shared__ float logits[48];

    av[tid]       = g_agg1[(size_t)t * HID + tid];   // lin_l input
    av[HID + tid] = g_h[(size_t)t * HID + tid];      // lin_r input (h[:B])
    __syncthreads();

    // 4 threads per output column; all 256 threads execute (c clamped) so shfl masks are full
    int c = tid >> 2; if (c > OUT_C - 1) c = OUT_C - 1;
    int p = tid & 3;
    const float* W = (p < 2) ? Wl1 : Wr1;
    int kbase = p * 128;
    int wbase = (p < 2) ? (kbase * OUT_C) : ((kbase - HID) * OUT_C);
    float s0 = 0.f, s1 = 0.f;
#pragma unroll 8
    for (int k = 0; k < 128; k += 2) {
        s0 += av[kbase + k]     * __ldg(&W[wbase + k * OUT_C + c]);
        s1 += av[kbase + k + 1] * __ldg(&W[wbase + (k + 1) * OUT_C + c]);
    }
    float s = s0 + s1;
    s += __shfl_xor_sync(0xffffffffu, s, 1);
    s += __shfl_xor_sync(0xffffffffu, s, 2);
    if (p == 0 && (tid >> 2) < OUT_C) logits[tid >> 2] = s + bl1[tid >> 2];
    __syncthreads();

    if (tid < 32) {  // warp 0 does log_softmax over 41 values
        float v0 = logits[tid];                                  // tid < 32 <= 41 always valid? tid<32<41 yes
        bool hi = (tid + 32) < OUT_C;
        float v1 = hi ? logits[tid + 32] : -3.4e38f;
        float mx = fmaxf(v0, v1);
#pragma unroll
        for (int o = 16; o > 0; o >>= 1)
            mx = fmaxf(mx, __shfl_xor_sync(0xffffffffu, mx, o));
        float es = expf(v0 - mx) + (hi ? expf(v1 - mx) : 0.f);
#pragma unroll
        for (int o = 16; o > 0; o >>= 1)
            es += __shfl_xor_sync(0xffffffffu, es, o);
        float lse = logf(es) + mx;
        out[(size_t)t * OUT_C + tid] = v0 - lse;
        if (hi) out[(size_t)t * OUT_C + tid + 32] = v1 - lse;
    }
}

// ---------------- launch ----------------
extern "C" void kernel_launch(void* const* d_in, const int* in_sizes, int n_in,
                              void* d_out, int out_size) {
    const float* x    = (const float*)d_in[0];
    const float* Wl0  = (const float*)d_in[1];
    const float* bl0  = (const float*)d_in[2];
    const float* Wr0  = (const float*)d_in[3];
    const float* Wl1  = (const float*)d_in[4];
    const float* bl1  = (const float*)d_in[5];
    const float* Wr1  = (const float*)d_in[6];
    const int*   src0 = (const int*)d_in[7];
    const int*   dst0 = (const int*)d_in[8];
    const int*   src1 = (const int*)d_in[9];
    const int*   dst1 = (const int*)d_in[10];
    float* out = (float*)d_out;

    // segment boundaries (dst sorted)
    seg_kernel<<<(N1 + 1 + 255) / 256, 256>>>(dst0, E0, N1, 0);
    seg_kernel<<<(BSZ + 1 + 255) / 256, 256>>>(dst1, E1, BSZ, 1);

    // concat weights
    wcat_kernel<<<KCAT, 256>>>(Wl0, Wr0);

    // layer 0
    agg0_kernel<<<N1, 256>>>(x, src0);
    gemm0_kernel<<<dim3(N1 / BM, HID / BN), 256>>>(bl0);

    // layer 1
    agg1_kernel<<<BSZ, 256>>>(src1);
    out_kernel<<<BSZ, 256>>>(Wl1, Wr1, bl1, out);
}

// round 8
// speedup vs baseline: 1.4047x; 1.4047x over previous
#include <cuda_runtime.h>
#include <cuda_bf16.h>
#include <cstdint>

// Problem constants (fixed shapes)
#define N0    260000
#define N1    10240
#define BSZ   1024
#define E0    256000
#define E1    10240
#define IN_C  602
#define HID   256
#define OUT_C 41

// Concat-K for layer-0 GEMM: [0,602)=agg, [602,608)=0, [608,1210)=x_tgt, [1210,1216)=0
#define KCAT  1216

// ---------------- scratch (static device memory; no allocation) ----------------
__device__ __align__(16) float g_acat[(size_t)N1 * KCAT];   // 49.8 MB concat A (fp32)
__device__ __align__(16) float g_bh[(size_t)HID * KCAT];    // 1.2 MB  B^T hi (tf32 bits as float)
__device__ __align__(16) float g_bl[(size_t)HID * KCAT];    // 1.2 MB  B^T lo
__device__ __align__(16) float g_h[(size_t)N1 * HID];       // 10.5 MB layer-0 output (post ReLU)
__device__ __align__(16) float g_agg1[(size_t)BSZ * HID];   // 1 MB    layer-1 aggregation
__device__ int g_seg0[N1 + 1];
__device__ int g_seg1[BSZ + 1];

// ---------------- helpers ----------------
__device__ __forceinline__ uint32_t smem_u32(const void* p) {
    uint32_t a;
    asm("{ .reg .u64 t; cvta.to.shared.u64 t, %1; cvt.u32.u64 %0, t; }" : "=r"(a) : "l"(p));
    return a;
}
// tf32 split: v -> hi (tf32-rounded), lo (tf32-rounded residual)
__device__ __forceinline__ void split1(float v, float& h, float& l) {
    uint32_t hb; asm("cvt.rna.tf32.f32 %0, %1;" : "=r"(hb) : "f"(v));
    h = __uint_as_float(hb);
    float r = v - h;
    uint32_t lb; asm("cvt.rna.tf32.f32 %0, %1;" : "=r"(lb) : "f"(r));
    l = __uint_as_float(lb);
}
#define MMA_TF32(dd, aa, bb)                                                  \
    asm volatile("mma.sync.aligned.m16n8k8.row.col.f32.tf32.tf32.f32 "        \
        "{%0,%1,%2,%3}, {%4,%5,%6,%7}, {%8,%9}, {%0,%1,%2,%3};"               \
        : "+f"(dd[0]), "+f"(dd[1]), "+f"(dd[2]), "+f"(dd[3])                  \
        : "r"(aa[0]), "r"(aa[1]), "r"(aa[2]), "r"(aa[3]), "r"(bb[0]), "r"(bb[1]))

#define CP_ASYNC16(smem, gptr)                                                \
    asm volatile("cp.async.cg.shared.global [%0], [%1], 16;"                  \
        :: "r"(smem), "l"(gptr) : "memory")

// ---------------- segment boundaries via binary search (dst is sorted) ----------------
__global__ void seg_kernel(const int* __restrict__ dst, int E, int Nt, int which) {
    int t = blockIdx.x * blockDim.x + threadIdx.x;
    if (t > Nt) return;
    int lo = 0, hi = E;
    while (lo < hi) {
        int mid = (lo + hi) >> 1;
        if (dst[mid] < t) lo = mid + 1; else hi = mid;
    }
    if (which == 0) g_seg0[t] = lo; else g_seg1[t] = lo;
}

// ---------------- B prep: transpose concat weight into [n][k], split hi/lo ----------------
// tile transpose: grid (38, 8), block 256. tile = 32k x 32n.
__global__ void __launch_bounds__(256) bprep_kernel(const float* __restrict__ Wl0,
                                                    const float* __restrict__ Wr0) {
    __shared__ float th[32][33], tl[32][33];
    int k0 = blockIdx.x * 32, n0 = blockIdx.y * 32;
    int tn = threadIdx.x & 31, tk = threadIdx.x >> 5;   // 8 k-rows per pass
#pragma unroll
    for (int i = 0; i < 4; i++) {
        int k = k0 + tk + i * 8;
        float w = 0.f;
        if (k < IN_C)                  w = Wl0[(size_t)k * HID + n0 + tn];
        else if (k >= 608 && k < 1210) w = Wr0[(size_t)(k - 608) * HID + n0 + tn];
        float h, l; split1(w, h, l);
        th[tk + i * 8][tn] = h;
        tl[tk + i * 8][tn] = l;
    }
    __syncthreads();
    // write transposed: row n, col k contiguous
    int wk = threadIdx.x & 31, wn = threadIdx.x >> 5;
#pragma unroll
    for (int i = 0; i < 4; i++) {
        int n = n0 + wn + i * 8;
        g_bh[(size_t)n * KCAT + k0 + wk] = th[wk][wn + i * 8];
        g_bl[(size_t)n * KCAT + k0 + wk] = tl[wk][wn + i * 8];
    }
}

// ---------------- layer-0 mean aggregation + x_tgt copy into concat A ----------------
__global__ void __launch_bounds__(256) agg0_kernel(const float* __restrict__ x,
                                                   const int* __restrict__ src) {
    int t = blockIdx.x;
    int tid = threadIdx.x;
    int s = g_seg0[t], e = g_seg0[t + 1];
    __shared__ int sidx[256];

    float2 a01 = {0.f, 0.f}, a23 = {0.f, 0.f};
    for (int base = s; base < e; base += 256) {
        int n = min(256, e - base);
        if (tid < n) sidx[tid] = src[base + tid];
        __syncthreads();
#pragma unroll 4
        for (int i = 0; i < n; i++) {
            const float2* row = (const float2*)(x + (size_t)sidx[i] * IN_C);
            float2 v = __ldg(&row[tid]);
            a01.x += v.x; a01.y += v.y;
            if (tid < 45) {
                float2 w = __ldg(&row[256 + tid]);
                a23.x += w.x; a23.y += w.y;
            }
        }
        __syncthreads();
    }
    float inv = (e > s) ? (1.0f / (float)(e - s)) : 1.0f;
    float2* dst = (float2*)(g_acat + (size_t)t * KCAT);
    dst[tid] = make_float2(a01.x * inv, a01.y * inv);
    if (tid < 45) dst[256 + tid] = make_float2(a23.x * inv, a23.y * inv);
    if (tid < 3)  dst[301 + tid] = make_float2(0.f, 0.f);      // cols 602..607

    const float2* xr = (const float2*)(x + (size_t)t * IN_C);
    dst[304 + tid] = __ldg(&xr[tid]);                          // cols 608..1119
    if (tid < 45) dst[560 + tid] = __ldg(&xr[256 + tid]);      // cols 1120..1209
    if (tid < 3)  dst[605 + tid] = make_float2(0.f, 0.f);      // cols 1210..1215
}

// ---------------- layer-0 GEMM: h = relu(Acat @ Wcat + b) via tf32 mma.sync, 3xTF32 ----------------
// CTA 128x64, BK=32, 256 thr (8 warps, warp tile 32x32), double-buffered SMEM.
// Stage (floats): A_hi[8][128][4] @0 (4096) | A_lo @4096 | B_hi[8][65*4] @8192 (2080) | B_lo @10272
#define SSTRIDE 12352
#define NCHUNK  38
__global__ void __launch_bounds__(256, 2) gemm0_mma(const float* __restrict__ bias) {
    extern __shared__ float sm[];
    uint32_t sb = smem_u32(sm);
    int tid = threadIdx.x;
    int lane = tid & 31, wid = tid >> 5;
    int mw = (wid >> 1) * 32, nw = (wid & 1) * 32;
    int l4 = lane >> 2, lk = lane & 3;
    int m0 = blockIdx.x * 128, n0 = blockIdx.y * 64;

    // producer A: thread -> row pm (0..127), k-half (tid&1)*16; 4 float4 per chunk
    int pm = tid >> 1;
    int pk4 = (tid & 1) * 4;
    const float4* Ag = (const float4*)(g_acat + (size_t)(m0 + pm) * KCAT);
    // producer B: thread -> row pn (0..63), 2 k4-groups; cp.async 16B x4 per chunk
    int pn = tid >> 2;
    int pb4 = (tid & 3) * 2;
    const float4* Bhg = (const float4*)(g_bh + (size_t)(n0 + pn) * KCAT);
    const float4* Blg = (const float4*)(g_bl + (size_t)(n0 + pn) * KCAT);

    float4 ra[4];

#define LDG_A(c)                                                         \
    {                                                                    \
        _Pragma("unroll")                                                \
        for (int j = 0; j < 4; j++) ra[j] = __ldg(&Ag[(c) * 8 + pk4 + j]); \
    }
#define STS_A(st)                                                        \
    {                                                                    \
        float4* Ah4 = (float4*)(sm + (st) * SSTRIDE);                    \
        float4* Al4 = (float4*)(sm + (st) * SSTRIDE + 4096);             \
        _Pragma("unroll")                                                \
        for (int j = 0; j < 4; j++) {                                    \
            float4 h, l;                                                 \
            split1(ra[j].x, h.x, l.x); split1(ra[j].y, h.y, l.y);        \
            split1(ra[j].z, h.z, l.z); split1(ra[j].w, h.w, l.w);        \
            Ah4[(pk4 + j) * 128 + pm] = h;                               \
            Al4[(pk4 + j) * 128 + pm] = l;                               \
        }                                                                \
    }
#define CP_B(c, st)                                                      \
    {                                                                    \
        uint32_t bhb = sb + ((st) * SSTRIDE + 8192) * 4;                 \
        uint32_t blb = sb + ((st) * SSTRIDE + 10272) * 4;                \
        _Pragma("unroll")                                                \
        for (int j = 0; j < 2; j++) {                                    \
            int k4 = pb4 + j;                                            \
            uint32_t doff = (uint32_t)(k4 * 65 + pn) * 16;               \
            CP_ASYNC16(bhb + doff, &Bhg[(c) * 8 + k4]);                  \
            CP_ASYNC16(blb + doff, &Blg[(c) * 8 + k4]);                  \
        }                                                                \
    }

    LDG_A(0); CP_B(0, 0); STS_A(0);
    asm volatile("cp.async.commit_group;" ::: "memory");
    asm volatile("cp.async.wait_group 0;" ::: "memory");
    __syncthreads();

    float d[2][4][4] = {};

    for (int c = 0; c < NCHUNK; c++) {
        int st = c & 1;
        if (c + 1 < NCHUNK) { LDG_A(c + 1); CP_B(c + 1, st ^ 1); }

        const float* Ah = sm + st * SSTRIDE;
        const float* Al = Ah + 4096;
        const float* Bh = sm + st * SSTRIDE + 8192;
        const float* Bl = sm + st * SSTRIDE + 10272;

#pragma unroll
        for (int ks = 0; ks < 4; ks++) {
            uint32_t ah[2][4], al[2][4], bhf[4][2], blf[4][2];
            int abase = 2 * ks * 512;
            int bbase = 2 * ks * 260;
#pragma unroll
            for (int mi = 0; mi < 2; mi++) {
                int m = mw + mi * 16 + l4;
                ah[mi][0] = __float_as_uint(Ah[abase + m * 4 + lk]);
                ah[mi][1] = __float_as_uint(Ah[abase + (m + 8) * 4 + lk]);
                ah[mi][2] = __float_as_uint(Ah[abase + 512 + m * 4 + lk]);
                ah[mi][3] = __float_as_uint(Ah[abase + 512 + (m + 8) * 4 + lk]);
                al[mi][0] = __float_as_uint(Al[abase + m * 4 + lk]);
                al[mi][1] = __float_as_uint(Al[abase + (m + 8) * 4 + lk]);
                al[mi][2] = __float_as_uint(Al[abase + 512 + m * 4 + lk]);
                al[mi][3] = __float_as_uint(Al[abase + 512 + (m + 8) * 4 + lk]);
            }
#pragma unroll
            for (int ni = 0; ni < 4; ni++) {
                int n = nw + ni * 8 + l4;
                bhf[ni][0] = __float_as_uint(Bh[bbase + n * 4 + lk]);
                bhf[ni][1] = __float_as_uint(Bh[bbase + 260 + n * 4 + lk]);
                blf[ni][0] = __float_as_uint(Bl[bbase + n * 4 + lk]);
                blf[ni][1] = __float_as_uint(Bl[bbase + 260 + n * 4 + lk]);
            }
#pragma unroll
            for (int mi = 0; mi < 2; mi++)
#pragma unroll
                for (int ni = 0; ni < 4; ni++) {
                    MMA_TF32(d[mi][ni], ah[mi], bhf[ni]);   // hi*hi
                    MMA_TF32(d[mi][ni], al[mi], bhf[ni]);   // lo*hi
                    MMA_TF32(d[mi][ni], ah[mi], blf[ni]);   // hi*lo
                }
        }

        if (c + 1 < NCHUNK) {
            STS_A(st ^ 1);
            asm volatile("cp.async.commit_group;" ::: "memory");
            asm volatile("cp.async.wait_group 0;" ::: "memory");
            __syncthreads();
        }
    }

    // epilogue: bias + relu, float2 stores
#pragma unroll
    for (int mi = 0; mi < 2; mi++) {
        int m = m0 + mw + mi * 16 + l4;
#pragma unroll
        for (int ni = 0; ni < 4; ni++) {
            int n = n0 + nw + ni * 8 + 2 * lk;
            float b0 = __ldg(&bias[n]), b1 = __ldg(&bias[n + 1]);
            float2 v0 = make_float2(fmaxf(d[mi][ni][0] + b0, 0.f),
                                    fmaxf(d[mi][ni][1] + b1, 0.f));
            *(float2*)&g_h[(size_t)m * HID + n] = v0;
            float2 v1 = make_float2(fmaxf(d[mi][ni][2] + b0, 0.f),
                                    fmaxf(d[mi][ni][3] + b1, 0.f));
            *(float2*)&g_h[(size_t)(m + 8) * HID + n] = v1;
        }
    }
}

// ---------------- layer-1 mean aggregation ----------------
__global__ void __launch_bounds__(256) agg1_kernel(const int* __restrict__ src) {
    int t = blockIdx.x;
    int tid = threadIdx.x;
    int s = g_seg1[t], e = g_seg1[t + 1];
    __shared__ int sidx[256];
    float a = 0.f;
    for (int base = s; base < e; base += 256) {
        int n = min(256, e - base);
        if (tid < n) sidx[tid] = src[base + tid];
        __syncthreads();
#pragma unroll 4
        for (int i = 0; i < n; i++)
            a += g_h[(size_t)sidx[i] * HID + tid];
        __syncthreads();
    }
    float inv = (e > s) ? (1.0f / (float)(e - s)) : 1.0f;
    g_agg1[(size_t)t * HID + tid] = a * inv;
}

// ---------------- layer-1 GEMM + log_softmax, one CTA per output row ----------------
__global__ void __launch_bounds__(256) out_kernel(const float* __restrict__ Wl1,
                                                  const float* __restrict__ Wr1,
                                                  const float* __restrict__ bl1,
                                                  float* __restrict__ out) {
    int t = blockIdx.x;
    int tid = threadIdx.x;
    __shared__ float av[2 * HID];
    __shared__ float logits[48];

    av[tid]       = g_agg1[(size_t)t * HID + tid];   // lin_l input
    av[HID + tid] = g_h[(size_t)t * HID + tid];      // lin_r input (h[:B])
    __syncthreads();

    int c = tid >> 2; if (c > OUT_C - 1) c = OUT_C - 1;
    int p = tid & 3;
    const float* W = (p < 2) ? Wl1 : Wr1;
    int kbase = p * 128;
    int wbase = (p < 2) ? (kbase * OUT_C) : ((kbase - HID) * OUT_C);
    float s0 = 0.f, s1 = 0.f;
#pragma unroll 8
    for (int k = 0; k < 128; k += 2) {
        s0 += av[kbase + k]     * __ldg(&W[wbase + k * OUT_C + c]);
        s1 += av[kbase + k + 1] * __ldg(&W[wbase + (k + 1) * OUT_C + c]);
    }
    float s = s0 + s1;
    s += __shfl_xor_sync(0xffffffffu, s, 1);
    s += __shfl_xor_sync(0xffffffffu, s, 2);
    if (p == 0 && (tid >> 2) < OUT_C) logits[tid >> 2] = s + bl1[tid >> 2];
    __syncthreads();

    if (tid < 32) {
        float v0 = logits[tid];
        bool hi = (tid + 32) < OUT_C;
        float v1 = hi ? logits[tid + 32] : -3.4e38f;
        float mx = fmaxf(v0, v1);
#pragma unroll
        for (int o = 16; o > 0; o >>= 1)
            mx = fmaxf(mx, __shfl_xor_sync(0xffffffffu, mx, o));
        float es = expf(v0 - mx) + (hi ? expf(v1 - mx) : 0.f);
#pragma unroll
        for (int o = 16; o > 0; o >>= 1)
            es += __shfl_xor_sync(0xffffffffu, es, o);
        float lse = logf(es) + mx;
        out[(size_t)t * OUT_C + tid] = v0 - lse;
        if (hi) out[(size_t)t * OUT_C + tid + 32] = v1 - lse;
    }
}

// ---------------- launch ----------------
extern "C" void kernel_launch(void* const* d_in, const int* in_sizes, int n_in,
                              void* d_out, int out_size) {
    const float* x    = (const float*)d_in[0];
    const float* Wl0  = (const float*)d_in[1];
    const float* bl0  = (const float*)d_in[2];
    const float* Wr0  = (const float*)d_in[3];
    const float* Wl1  = (const float*)d_in[4];
    const float* bl1  = (const float*)d_in[5];
    const float* Wr1  = (const float*)d_in[6];
    const int*   src0 = (const int*)d_in[7];
    const int*   dst0 = (const int*)d_in[8];
    const int*   src1 = (const int*)d_in[9];
    const int*   dst1 = (const int*)d_in[10];
    float* out = (float*)d_out;

    const int smem_bytes = 2 * SSTRIDE * 4;   // 98816
    cudaFuncSetAttribute(gemm0_mma, cudaFuncAttributeMaxDynamicSharedMemorySize, smem_bytes);

    // segment boundaries (dst sorted)
    seg_kernel<<<(N1 + 1 + 255) / 256, 256>>>(dst0, E0, N1, 0);
    seg_kernel<<<(BSZ + 1 + 255) / 256, 256>>>(dst1, E1, BSZ, 1);

    // B^T hi/lo concat weights
    bprep_kernel<<<dim3(KCAT / 32, HID / 32), 256>>>(Wl0, Wr0);

    // layer 0
    agg0_kernel<<<N1, 256>>>(x, src0);
    gemm0_mma<<<dim3(N1 / 128, HID / 64), 256, smem_bytes>>>(bl0);

    // layer 1
    agg1_kernel<<<BSZ, 256>>>(src1);
    out_kernel<<<BSZ, 256>>>(Wl1, Wr1, bl1, out);
}